// round 12
// baseline (speedup 1.0000x reference)
#include <cuda_runtime.h>
#include <cuda_fp16.h>
#include <cstdint>

// Problem constants (FractalMoE: E=32, H=512, TOPK=4, B=2, S=1024)
#define NTOK   2048
#define HDIM   512
#define H2DIM  1024
#define NEXP   32
#define TOPK   4
#define NSLOT  (NTOK*TOPK)   // 8192
#define KC     64            // K-chunk per stage (64 halves = 128B/row)
#define NSTG   3             // cp.async pipeline depth
#define NCVT1  256           // wg/wu convert slices (128 + 128)
#define GRID   296           // all CTAs co-resident (2/SM x 148)

// ---------------- scratch (device globals; no allocation allowed) ----------
__device__ int    g_sel[NSLOT];
__device__ float  g_wn[NSLOT];
__device__ int    g_off[NEXP+1];
__device__ int    g_tileoff[NEXP+1];
__device__ int    g_tok[NSLOT];
__device__ float  g_tw[NSLOT];
__device__ int    g_cvtflag[NCVT1];                    // wg/wu slice converted
__device__ __half g_hidden [(size_t)NSLOT*H2DIM];      // 16 MiB fp16
__device__ __half g_xh [(size_t)NTOK*HDIM];            // 2 MiB fp16 x
__device__ __half g_wgh[(size_t)NEXP*H2DIM*HDIM];      // 32 MiB fp16 w_gate
__device__ __half g_wuh[(size_t)NEXP*H2DIM*HDIM];      // 32 MiB fp16 w_up
__device__ __half g_wdh[(size_t)NEXP*HDIM*H2DIM];      // 32 MiB fp16 w_down

// ---------------- helpers ----------------------------------------------------
__device__ __forceinline__ uint32_t smem_u32(const void* p) {
    uint32_t a;
    asm("{ .reg .u64 t; cvta.to.shared.u64 t, %1; cvt.u32.u64 %0, t; }"
        : "=r"(a) : "l"(p));
    return a;
}
__device__ __forceinline__ void cpa16(uint32_t dst, const void* src) {
    asm volatile("cp.async.cg.shared.global [%0], [%1], 16;" :: "r"(dst), "l"(src));
}
#define CP_COMMIT() asm volatile("cp.async.commit_group;" ::: "memory")
#define CP_WAIT1()  asm volatile("cp.async.wait_group 1;" ::: "memory")

__device__ __forceinline__ void ldsm4(uint32_t r[4], uint32_t addr) {
    asm volatile("ldmatrix.sync.aligned.m8n8.x4.shared.b16 {%0,%1,%2,%3}, [%4];"
        : "=r"(r[0]), "=r"(r[1]), "=r"(r[2]), "=r"(r[3]) : "r"(addr));
}
__device__ __forceinline__ void ldsm2(uint32_t r[2], uint32_t addr) {
    asm volatile("ldmatrix.sync.aligned.m8n8.x2.shared.b16 {%0,%1}, [%2];"
        : "=r"(r[0]), "=r"(r[1]) : "r"(addr));
}

// m16n8k16 row.col f32.f16.f16.f32
__device__ __forceinline__ void mma16(float d[4], const uint32_t a[4], const uint32_t b[2]) {
    asm volatile(
        "mma.sync.aligned.m16n8k16.row.col.f32.f16.f16.f32 "
        "{%0,%1,%2,%3},{%4,%5,%6,%7},{%8,%9},{%0,%1,%2,%3};"
        : "+f"(d[0]), "+f"(d[1]), "+f"(d[2]), "+f"(d[3])
        : "r"(a[0]), "r"(a[1]), "r"(a[2]), "r"(a[3]), "r"(b[0]), "r"(b[1]));
}

// Panels: row-major, 64 halves (128B) per row. 16B block b of row r stored at
// block b ^ (r&7). Conflict-free for cp.async 16B writes and LDSM row reads.

extern __shared__ char smem_dyn[];

// ---------------- 0) fp32 -> fp16 (RN) convert (x, wd) ----------------------
__global__ void cvt_kernel(const float4* __restrict__ src, uint4* __restrict__ dst, int n8) {
    int i = blockIdx.x*blockDim.x + threadIdx.x;
    if (i >= n8) return;
    float4 a = src[2*i], b = src[2*i+1];
    __half2 h0 = __floats2half2_rn(a.x, a.y);
    __half2 h1 = __floats2half2_rn(a.z, a.w);
    __half2 h2 = __floats2half2_rn(b.x, b.y);
    __half2 h3 = __floats2half2_rn(b.z, b.w);
    uint4 o;
    o.x = *(uint32_t*)&h0; o.y = *(uint32_t*)&h1;
    o.z = *(uint32_t*)&h2; o.w = *(uint32_t*)&h3;
    dst[i] = o;
}

// ---------------- 1) gating: softmax + top-4 + renormalize -----------------
__global__ void gate_kernel(const float* __restrict__ x, const float* __restrict__ gw) {
    float* sgw = (float*)smem_dyn;   // [32][512] = 64KB
    for (int i = threadIdx.x; i < NEXP*HDIM/4; i += blockDim.x)
        ((float4*)sgw)[i] = ((const float4*)gw)[i];
    __syncthreads();
    int warp = threadIdx.x >> 5, lane = threadIdx.x & 31;
    for (int tt = 0; tt < 2; tt++) {
        int t = blockIdx.x*16 + warp*2 + tt;
        const float4* xv = (const float4*)(x + (size_t)t * HDIM);
        const float4* gv = (const float4*)(sgw + lane * HDIM);
        float acc = 0.f;
#pragma unroll 4
        for (int k = 0; k < HDIM/4; k++) {
            float4 a = xv[k], b = gv[k];
            acc += a.x*b.x + a.y*b.y + a.z*b.z + a.w*b.w;
        }
        float m = acc;
        for (int o = 16; o; o >>= 1) m = fmaxf(m, __shfl_xor_sync(0xffffffffu, m, o));
        float p = __expf(acc - m);
        float s = p;
        for (int o = 16; o; o >>= 1) s += __shfl_xor_sync(0xffffffffu, s, o);
        float prob = p / s;

        float cur = prob, wsum = 0.f;
        float wv[TOPK]; int iv[TOPK];
#pragma unroll
        for (int it = 0; it < TOPK; it++) {
            float v = cur; int idx = lane;
            for (int o = 16; o; o >>= 1) {
                float v2 = __shfl_xor_sync(0xffffffffu, v, o);
                int   i2 = __shfl_xor_sync(0xffffffffu, idx, o);
                if (v2 > v || (v2 == v && i2 < idx)) { v = v2; idx = i2; }
            }
            wv[it] = v; iv[it] = idx; wsum += v;
            if (lane == idx) cur = -1.0f;
        }
        if (lane == 0) {
#pragma unroll
            for (int it = 0; it < TOPK; it++) {
                g_sel[t*TOPK + it] = iv[it];
                g_wn [t*TOPK + it] = wv[it] / wsum;
            }
        }
    }
}

// ---------------- 2) routing (tiles of 128 rows) + cvt-flag reset -----------
__global__ void route_kernel() {
    __shared__ int cnt[NEXP], run[NEXP], off_s[NEXP+1];
    int tid = threadIdx.x;
    if (tid < NEXP) { cnt[tid] = 0; run[tid] = 0; }
    if (tid < NCVT1) g_cvtflag[tid] = 0;     // reset per replay
    __syncthreads();
    for (int i = tid; i < NSLOT; i += blockDim.x)
        atomicAdd(&cnt[g_sel[i]], 1);
    __syncthreads();
    if (tid == 0) {
        int o = 0, to = 0;
        for (int e = 0; e < NEXP; e++) {
            off_s[e] = o; g_off[e] = o; g_tileoff[e] = to;
            o  += cnt[e];
            to += (cnt[e] + 127) >> 7;
        }
        off_s[NEXP] = o; g_off[NEXP] = o; g_tileoff[NEXP] = to;
    }
    __syncthreads();
    for (int i = tid; i < NSLOT; i += blockDim.x) {
        int e = g_sel[i];
        int p = atomicAdd(&run[e], 1) + off_s[e];
        g_tok[p] = i >> 2;
        g_tw [p] = g_wn[i];
    }
}

// ---------------- 3) FFN1 (+ fused wg/wu convert, flag-gated) ---------------
// cvt items 0..255: slice s<128 -> wg rows [s*256, s*256+256); else wu.
// ffn1 item (tIdx,ht): needs wg/wu slice e*4 + (ht>>2).
// smem: rtok@0; A @1024 (3x16KB); G @50176 (3x8KB); U @74752 (3x8KB). tot 99328.
#define F1_A(s)  (1024  + (s)*16384)
#define F1_G(s)  (50176 + (s)*8192)
#define F1_U(s)  (74752 + (s)*8192)

__global__ __launch_bounds__(256, 2)
void ffn1_mma(const float* __restrict__ wg, const float* __restrict__ wu) {
    char* sm = smem_dyn;
    int* rtok = (int*)sm;
    const uint32_t sb = smem_u32(sm);
    const int tid = threadIdx.x, lane = tid & 31, wid = tid >> 5;
    const int wm = wid >> 1, wn = wid & 1;
    const int g0 = lane >> 2, q = lane & 3;
    const int n1 = g_tileoff[NEXP] * 16;

    const int ri    = lane & 7;
    const int miA   = lane >> 3;            // 0..3
    const int rowoA = (miA & 1) * 8;
    const int khA   = miA >> 1;
    const int mi2   = (lane >> 3) & 1;
    uint32_t aRow[2], bRow[4], axk[4], bxk[4];
#pragma unroll
    for (int m = 0; m < 2; m++) aRow[m] = (uint32_t)((wm*32 + m*16 + rowoA + ri) * 128);
#pragma unroll
    for (int n = 0; n < 4; n++) bRow[n] = (uint32_t)((wn*32 + n*8 + ri) * 128);
#pragma unroll
    for (int kt = 0; kt < 4; kt++) {
        axk[kt] = (uint32_t)((((kt<<1) | khA) ^ ri) << 4);
        bxk[kt] = (uint32_t)((((kt<<1) | mi2) ^ ri) << 4);
    }

    const int ar = tid >> 1;                 // A row 0..127
    const int ab = (tid & 1) * 4;
    const int wr_ = tid >> 2;                // G/U row 0..63
    const int wb = (tid & 3) * 2;

    for (int item = blockIdx.x; item < NCVT1 + n1; item += gridDim.x) {
        if (item < NCVT1) {
            // ---- convert one 256-row x 512-col slice of wg or wu -----------
            const int s = item & 127;
            const float4* src = (const float4*)((item < 128 ? wg : wu)
                                + (size_t)s*256*HDIM);
            uint4* dst = (uint4*)((item < 128 ? g_wgh : g_wuh)
                                + (size_t)s*256*HDIM);
            for (int i = tid; i < 256*HDIM/8; i += 256) {
                float4 a = src[2*i], b = src[2*i+1];
                __half2 h0 = __floats2half2_rn(a.x, a.y);
                __half2 h1 = __floats2half2_rn(a.z, a.w);
                __half2 h2 = __floats2half2_rn(b.x, b.y);
                __half2 h3 = __floats2half2_rn(b.z, b.w);
                uint4 o;
                o.x = *(uint32_t*)&h0; o.y = *(uint32_t*)&h1;
                o.z = *(uint32_t*)&h2; o.w = *(uint32_t*)&h3;
                dst[i] = o;
            }
            __threadfence();
            __syncthreads();
            if (tid == 0) atomicExch(&g_cvtflag[item], 1);
            continue;
        }
        const int it1  = item - NCVT1;
        const int tIdx = it1 >> 4;
        const int ht   = it1 & 15;
        int e = 0;
        while (g_tileoff[e+1] <= tIdx) e++;
        const int base  = g_off[e] + (tIdx - g_tileoff[e]) * 128;
        const int nrows = min(128, g_off[e+1] - base);
        const int slice = e*4 + (ht >> 2);

        // wait for the wg/wu slices this item reads
        __syncthreads();                      // also protects rtok/stage reuse
        if (tid == 0) {
            while (atomicAdd(&g_cvtflag[slice], 0)       != 1) __nanosleep(64);
            while (atomicAdd(&g_cvtflag[128 + slice], 0) != 1) __nanosleep(64);
        }
        __syncthreads();
        __threadfence();                      // acquire converted data
        if (tid < 128) rtok[tid] = g_tok[base + min(tid, nrows-1)];
        __syncthreads();

        const __half* xr  = g_xh + (size_t)rtok[ar]*HDIM;
        const __half* wgB = g_wgh + ((size_t)e*H2DIM + (size_t)ht*64) * HDIM + (size_t)wr_*HDIM;
        const __half* wuB = g_wuh + ((size_t)e*H2DIM + (size_t)ht*64) * HDIM + (size_t)wr_*HDIM;

        auto stage = [&](int c) {
            const int s = c % NSTG;
            const int kb = c * KC;            // halves
            uint32_t da = sb + F1_A(s) + ar*128;
#pragma unroll
            for (int i = 0; i < 4; i++)
                cpa16(da + ((ab+i) ^ (ar&7))*16, xr + kb + (ab+i)*8);
            uint32_t dg = sb + F1_G(s) + wr_*128;
            uint32_t du = sb + F1_U(s) + wr_*128;
#pragma unroll
            for (int i = 0; i < 2; i++) {
                cpa16(dg + ((wb+i) ^ (wr_&7))*16, wgB + kb + (wb+i)*8);
                cpa16(du + ((wb+i) ^ (wr_&7))*16, wuB + kb + (wb+i)*8);
            }
        };

        float accG[2][4][4] = {}, accU[2][4][4] = {};

        stage(0); CP_COMMIT();
        stage(1); CP_COMMIT();

        for (int c = 0; c < HDIM/KC; c++) {
            CP_WAIT1();
            __syncthreads();
            if (c + 2 < HDIM/KC) stage(c + 2);
            CP_COMMIT();

            const int s = c % NSTG;
            const uint32_t pA = sb + F1_A(s);
            const uint32_t pG = sb + F1_G(s);
            const uint32_t pU = sb + F1_U(s);
#pragma unroll
            for (int kt = 0; kt < 4; kt++) {   // 4 x k16 = 64 halves
                uint32_t a[2][4], bg[4][2], bu[4][2];
#pragma unroll
                for (int m = 0; m < 2; m++)
                    ldsm4(a[m], pA + aRow[m] + axk[kt]);
#pragma unroll
                for (int n = 0; n < 4; n++) {
                    ldsm2(bg[n], pG + bRow[n] + bxk[kt]);
                    ldsm2(bu[n], pU + bRow[n] + bxk[kt]);
                }
#pragma unroll
                for (int m = 0; m < 2; m++)
#pragma unroll
                    for (int n = 0; n < 4; n++) {
                        mma16(accG[m][n], a[m], bg[n]);
                        mma16(accU[m][n], a[m], bu[n]);
                    }
            }
        }
        // epilogue: silu(G)*U -> g_hidden fp16
        {
#pragma unroll
            for (int m = 0; m < 2; m++) {
#pragma unroll
                for (int half = 0; half < 2; half++) {
                    const int row = wm*32 + m*16 + g0 + half*8;
                    if (row < nrows) {
                        __half2* drow = (__half2*)(g_hidden + (size_t)(base+row)*H2DIM
                                                   + ht*64 + wn*32);
#pragma unroll
                        for (int n = 0; n < 4; n++) {
                            float gg0 = accG[m][n][half*2+0], gg1 = accG[m][n][half*2+1];
                            float uu0 = accU[m][n][half*2+0], uu1 = accU[m][n][half*2+1];
                            float h0 = uu0 * gg0 / (1.f + __expf(-gg0));
                            float h1 = uu1 * gg1 / (1.f + __expf(-gg1));
                            drow[n*4 + q] = __floats2half2_rn(h0, h1);
                        }
                    }
                }
            }
        }
    }
}

// ---------------- 4) FFN2: out[tok] += tw * (hidden Wd^T), fused combine ----
// tile 128 slots x 128 out. 8 warps 4m x 2n, warp tile 32x64. K=1024.
// B fragments via ldmatrix.x4 (2 n-tiles per instr). Epilogue: RED.F32 to out.
// smem: A @1024 (3x16KB); W @50176 (3x16KB). tot 99328.
#define F2_A(s)  (1024  + (s)*16384)
#define F2_W(s)  (50176 + (s)*16384)

__global__ __launch_bounds__(256, 2)
void ffn2_mma(float* __restrict__ out) {
    char* sm = smem_dyn;
    const uint32_t sb = smem_u32(sm);
    const int tid = threadIdx.x, lane = tid & 31, wid = tid >> 5;
    const int wm = wid >> 1, wn = wid & 1;
    const int g0 = lane >> 2, q = lane & 3;
    const int nitems = g_tileoff[NEXP] * 4;
    const int nchunk = H2DIM / KC;            // 16

    const int ri  = lane & 7;
    const int miA = lane >> 3;
    const int kh  = (lane >> 3) & 1;
    const int ntx = lane >> 4;
    uint32_t aRow[2], bRowP[4], axk[4], bxk[4];
#pragma unroll
    for (int m = 0; m < 2; m++)
        aRow[m] = (uint32_t)((wm*32 + m*16 + (miA & 1)*8 + ri) * 128);
#pragma unroll
    for (int p = 0; p < 4; p++)
        bRowP[p] = (uint32_t)((wn*64 + (2*p + ntx)*8 + ri) * 128);
#pragma unroll
    for (int kt = 0; kt < 4; kt++) {
        axk[kt] = (uint32_t)((((kt<<1) | (miA>>1)) ^ ri) << 4);
        bxk[kt] = (uint32_t)((((kt<<1) | kh) ^ ri) << 4);
    }

    const int ar = tid >> 1;                 // row 0..127 (A and W same map)
    const int ab = (tid & 1) * 4;

    for (int item = blockIdx.x; item < nitems; item += gridDim.x) {
        const int tIdx = item >> 2;
        const int ht   = item & 3;
        int e = 0;
        while (g_tileoff[e+1] <= tIdx) e++;
        const int base  = g_off[e] + (tIdx - g_tileoff[e]) * 128;
        const int nrows = min(128, g_off[e+1] - base);

        const __half* hr  = g_hidden + (size_t)(base + min(ar, nrows-1))*H2DIM;
        const __half* wdB = g_wdh + ((size_t)e*HDIM + (size_t)ht*128) * H2DIM + (size_t)ar*H2DIM;

        __syncthreads();                      // stage-buffer reuse fence

        auto stage = [&](int c) {
            const int s = c % NSTG;
            const int kb = c * KC;            // halves
            uint32_t da = sb + F2_A(s) + ar*128;
            uint32_t dw = sb + F2_W(s) + ar*128;
#pragma unroll
            for (int i = 0; i < 4; i++) {
                cpa16(da + ((ab+i) ^ (ar&7))*16, hr  + kb + (ab+i)*8);
                cpa16(dw + ((ab+i) ^ (ar&7))*16, wdB + kb + (ab+i)*8);
            }
        };

        float acc[2][8][4] = {};

        stage(0); CP_COMMIT();
        stage(1); CP_COMMIT();

        for (int c = 0; c < nchunk; c++) {
            CP_WAIT1();
            __syncthreads();
            if (c + 2 < nchunk) stage(c + 2);
            CP_COMMIT();

            const int s = c % NSTG;
            const uint32_t pA = sb + F2_A(s);
            const uint32_t pW = sb + F2_W(s);
#pragma unroll
            for (int kt = 0; kt < 4; kt++) {
                uint32_t a[2][4], bw[4][4];
#pragma unroll
                for (int m = 0; m < 2; m++)
                    ldsm4(a[m], pA + aRow[m] + axk[kt]);
#pragma unroll
                for (int p = 0; p < 4; p++)
                    ldsm4(bw[p], pW + bRowP[p] + bxk[kt]);
#pragma unroll
                for (int m = 0; m < 2; m++)
#pragma unroll
                    for (int p = 0; p < 4; p++)
#pragma unroll
                        for (int h = 0; h < 2; h++)
                            mma16(acc[m][2*p+h], a[m], &bw[p][2*h]);
            }
        }
        // epilogue: out[tok] += acc * tw  (RED.F32; combine fused)
        {
            const int q2 = q * 2;
#pragma unroll
            for (int m = 0; m < 2; m++) {
#pragma unroll
                for (int half = 0; half < 2; half++) {
                    const int row = wm*32 + m*16 + g0 + half*8;
                    if (row < nrows) {
                        const float tw = g_tw[base + row];
                        const int tok = g_tok[base + row];
                        float* drow = out + (size_t)tok*HDIM + ht*128 + wn*64;
#pragma unroll
                        for (int n = 0; n < 8; n++) {
                            atomicAdd(drow + n*8 + q2,     acc[m][n][half*2+0] * tw);
                            atomicAdd(drow + n*8 + q2 + 1, acc[m][n][half*2+1] * tw);
                        }
                    }
                }
            }
        }
    }
}

// ---------------- launch ----------------------------------------------------
extern "C" void kernel_launch(void* const* d_in, const int* in_sizes, int n_in,
                              void* d_out, int out_size) {
    const float* x  = (const float*)d_in[0];   // [2,1024,512]
    const float* gw = (const float*)d_in[1];   // [32,512]
    const float* wg = (const float*)d_in[2];   // [32,1024,512]
    const float* wu = (const float*)d_in[3];   // [32,1024,512]
    const float* wd = (const float*)d_in[4];   // [32,512,1024]
    float* out = (float*)d_out;                // [2,1024,512] f32

    static void *p_xh = nullptr, *p_wdh = nullptr;
    static cudaStream_t sA = nullptr, sB = nullptr;
    static cudaEvent_t evRoot = nullptr, evA = nullptr, evB = nullptr;
    if (!p_xh) {
        cudaGetSymbolAddress(&p_xh,  g_xh);
        cudaGetSymbolAddress(&p_wdh, g_wdh);
        cudaFuncSetAttribute(gate_kernel, cudaFuncAttributeMaxDynamicSharedMemorySize, 65536);
        cudaFuncSetAttribute(ffn1_mma,    cudaFuncAttributeMaxDynamicSharedMemorySize, 99328);
        cudaFuncSetAttribute(ffn2_mma,    cudaFuncAttributeMaxDynamicSharedMemorySize, 99328);
        cudaStreamCreateWithFlags(&sA, cudaStreamNonBlocking);
        cudaStreamCreateWithFlags(&sB, cudaStreamNonBlocking);
        cudaEventCreateWithFlags(&evRoot, cudaEventDisableTiming);
        cudaEventCreateWithFlags(&evA,    cudaEventDisableTiming);
        cudaEventCreateWithFlags(&evB,    cudaEventDisableTiming);
    }

    const int NW8 = NEXP*H2DIM*HDIM/8;   // 2097152
    const int NX8 = NTOK*HDIM/8;         // 131072

    // zero the output (ffn2 accumulates into it atomically)
    cudaMemsetAsync(out, 0, (size_t)out_size * sizeof(float), 0);

    // fork: branch A = gate+route (also resets cvt flags); branch B = wd cvt
    cudaEventRecord(evRoot, 0);
    cudaStreamWaitEvent(sA, evRoot, 0);
    cudaStreamWaitEvent(sB, evRoot, 0);

    gate_kernel <<<128, 256, 65536, sA>>>(x, gw);
    route_kernel<<<1, 256, 0, sA>>>();
    cudaEventRecord(evA, sA);

    cvt_kernel<<<NW8/256, 256, 0, sB>>>((const float4*)wd, (uint4*)p_wdh, NW8);
    cudaEventRecord(evB, sB);

    // main: only x conversion stays ahead of ffn1 (tiny)
    cvt_kernel<<<NX8/256, 256>>>((const float4*)x, (uint4*)p_xh, NX8);

    cudaStreamWaitEvent(0, evA, 0);      // join gate/route (+flag reset)
    ffn1_mma<<<GRID, 256, 99328>>>(wg, wu);   // wg/wu cvt fused inside
    cudaStreamWaitEvent(0, evB, 0);      // join wd convert
    ffn2_mma<<<GRID, 256, 99328>>>(out); // fused combine via atomics
}

// round 13
// speedup vs baseline: 1.0581x; 1.0581x over previous
#include <cuda_runtime.h>
#include <cuda_fp16.h>
#include <cstdint>

// Problem constants (FractalMoE: E=32, H=512, TOPK=4, B=2, S=1024)
#define NTOK   2048
#define HDIM   512
#define H2DIM  1024
#define NEXP   32
#define TOPK   4
#define NSLOT  (NTOK*TOPK)   // 8192
#define KC     64            // K-chunk per stage (64 halves = 128B/row)
#define NSTG   3             // cp.async pipeline depth

// ---------------- scratch (device globals; no allocation allowed) ----------
__device__ int    g_sel[NSLOT];
__device__ float  g_wn[NSLOT];
__device__ int    g_off[NEXP+1];
__device__ int    g_tileoff[NEXP+1];
__device__ int    g_tok[NSLOT];
__device__ float  g_tw[NSLOT];
__device__ __half g_hidden [(size_t)NSLOT*H2DIM];      // 16 MiB fp16
__device__ __half g_xh [(size_t)NTOK*HDIM];            // 2 MiB fp16 x
__device__ __half g_wgh[(size_t)NEXP*H2DIM*HDIM];      // 32 MiB fp16 w_gate
__device__ __half g_wuh[(size_t)NEXP*H2DIM*HDIM];      // 32 MiB fp16 w_up
__device__ __half g_wdh[(size_t)NEXP*HDIM*H2DIM];      // 32 MiB fp16 w_down

// ---------------- helpers ----------------------------------------------------
__device__ __forceinline__ uint32_t smem_u32(const void* p) {
    uint32_t a;
    asm("{ .reg .u64 t; cvta.to.shared.u64 t, %1; cvt.u32.u64 %0, t; }"
        : "=r"(a) : "l"(p));
    return a;
}
__device__ __forceinline__ void cpa16(uint32_t dst, const void* src) {
    asm volatile("cp.async.cg.shared.global [%0], [%1], 16;" :: "r"(dst), "l"(src));
}
#define CP_COMMIT() asm volatile("cp.async.commit_group;" ::: "memory")
#define CP_WAIT1()  asm volatile("cp.async.wait_group 1;" ::: "memory")

__device__ __forceinline__ void ldsm4(uint32_t r[4], uint32_t addr) {
    asm volatile("ldmatrix.sync.aligned.m8n8.x4.shared.b16 {%0,%1,%2,%3}, [%4];"
        : "=r"(r[0]), "=r"(r[1]), "=r"(r[2]), "=r"(r[3]) : "r"(addr));
}
__device__ __forceinline__ void ldsm2(uint32_t r[2], uint32_t addr) {
    asm volatile("ldmatrix.sync.aligned.m8n8.x2.shared.b16 {%0,%1}, [%2];"
        : "=r"(r[0]), "=r"(r[1]) : "r"(addr));
}

// m16n8k16 row.col f32.f16.f16.f32
__device__ __forceinline__ void mma16(float d[4], const uint32_t a[4], const uint32_t b[2]) {
    asm volatile(
        "mma.sync.aligned.m16n8k16.row.col.f32.f16.f16.f32 "
        "{%0,%1,%2,%3},{%4,%5,%6,%7},{%8,%9},{%0,%1,%2,%3};"
        : "+f"(d[0]), "+f"(d[1]), "+f"(d[2]), "+f"(d[3])
        : "r"(a[0]), "r"(a[1]), "r"(a[2]), "r"(a[3]), "r"(b[0]), "r"(b[1]));
}

// Panels: row-major, 64 halves (128B) per row. 16B block b of row r stored at
// block b ^ (r&7). Conflict-free for cp.async 16B writes and LDSM row reads.

extern __shared__ char smem_dyn[];

// ---------------- 0) fp32 -> fp16 (RN) convert ------------------------------
__global__ void cvt_kernel(const float4* __restrict__ src, uint4* __restrict__ dst, int n8) {
    int i = blockIdx.x*blockDim.x + threadIdx.x;
    if (i >= n8) return;
    float4 a = src[2*i], b = src[2*i+1];
    __half2 h0 = __floats2half2_rn(a.x, a.y);
    __half2 h1 = __floats2half2_rn(a.z, a.w);
    __half2 h2 = __floats2half2_rn(b.x, b.y);
    __half2 h3 = __floats2half2_rn(b.z, b.w);
    uint4 o;
    o.x = *(uint32_t*)&h0; o.y = *(uint32_t*)&h1;
    o.z = *(uint32_t*)&h2; o.w = *(uint32_t*)&h3;
    dst[i] = o;
}

// ---------------- 1) gating: softmax + top-4 + renorm; also emits fp16 x ----
__global__ void gate_kernel(const float* __restrict__ x, const float* __restrict__ gw) {
    float* sgw = (float*)smem_dyn;   // [32][512] = 64KB
    for (int i = threadIdx.x; i < NEXP*HDIM/4; i += blockDim.x)
        ((float4*)sgw)[i] = ((const float4*)gw)[i];

    // by-product: convert this block's 16 tokens to fp16 (x -> g_xh)
    {
        const float2* xblk = (const float2*)(x + (size_t)blockIdx.x*16*HDIM);
        __half2* dst = (__half2*)(g_xh + (size_t)blockIdx.x*16*HDIM);
        for (int i = threadIdx.x; i < 16*HDIM/2; i += blockDim.x) {
            float2 v = xblk[i];
            dst[i] = __floats2half2_rn(v.x, v.y);
        }
    }
    __syncthreads();
    int warp = threadIdx.x >> 5, lane = threadIdx.x & 31;
    for (int tt = 0; tt < 2; tt++) {
        int t = blockIdx.x*16 + warp*2 + tt;
        const float4* xv = (const float4*)(x + (size_t)t * HDIM);
        const float4* gv = (const float4*)(sgw + lane * HDIM);
        float acc = 0.f;
#pragma unroll 4
        for (int k = 0; k < HDIM/4; k++) {
            float4 a = xv[k], b = gv[k];
            acc += a.x*b.x + a.y*b.y + a.z*b.z + a.w*b.w;
        }
        float m = acc;
        for (int o = 16; o; o >>= 1) m = fmaxf(m, __shfl_xor_sync(0xffffffffu, m, o));
        float p = __expf(acc - m);
        float s = p;
        for (int o = 16; o; o >>= 1) s += __shfl_xor_sync(0xffffffffu, s, o);
        float prob = p / s;

        float cur = prob, wsum = 0.f;
        float wv[TOPK]; int iv[TOPK];
#pragma unroll
        for (int it = 0; it < TOPK; it++) {
            float v = cur; int idx = lane;
            for (int o = 16; o; o >>= 1) {
                float v2 = __shfl_xor_sync(0xffffffffu, v, o);
                int   i2 = __shfl_xor_sync(0xffffffffu, idx, o);
                if (v2 > v || (v2 == v && i2 < idx)) { v = v2; idx = i2; }
            }
            wv[it] = v; iv[it] = idx; wsum += v;
            if (lane == idx) cur = -1.0f;
        }
        if (lane == 0) {
#pragma unroll
            for (int it = 0; it < TOPK; it++) {
                g_sel[t*TOPK + it] = iv[it];
                g_wn [t*TOPK + it] = wv[it] / wsum;
            }
        }
    }
}

// ---------------- 2) routing (tiles of 128 rows) ----------------------------
__global__ void route_kernel() {
    __shared__ int cnt[NEXP], run[NEXP], off_s[NEXP+1];
    int tid = threadIdx.x;
    if (tid < NEXP) { cnt[tid] = 0; run[tid] = 0; }
    __syncthreads();
    for (int i = tid; i < NSLOT; i += blockDim.x)
        atomicAdd(&cnt[g_sel[i]], 1);
    __syncthreads();
    if (tid == 0) {
        int o = 0, to = 0;
        for (int e = 0; e < NEXP; e++) {
            off_s[e] = o; g_off[e] = o; g_tileoff[e] = to;
            o  += cnt[e];
            to += (cnt[e] + 127) >> 7;
        }
        off_s[NEXP] = o; g_off[NEXP] = o; g_tileoff[NEXP] = to;
    }
    __syncthreads();
    for (int i = tid; i < NSLOT; i += blockDim.x) {
        int e = g_sel[i];
        int p = atomicAdd(&run[e], 1) + off_s[e];
        g_tok[p] = i >> 2;
        g_tw [p] = g_wn[i];
    }
}

// ---------------- 3) FFN1: hidden = silu(x Wg^T) * (x Wu^T) -----------------
// tile 128 tok x 64 hid (dual G/U). 8 warps 4m x 2n, warp tile 32x32/matrix.
// smem: rtok@0; A @1024 (3x16KB); G @50176 (3x8KB); U @74752 (3x8KB). tot 99328.
#define F1_A(s)  (1024  + (s)*16384)
#define F1_G(s)  (50176 + (s)*8192)
#define F1_U(s)  (74752 + (s)*8192)

__global__ __launch_bounds__(256)
void ffn1_mma() {
    char* sm = smem_dyn;
    int* rtok = (int*)sm;
    const uint32_t sb = smem_u32(sm);
    const int tid = threadIdx.x, lane = tid & 31, wid = tid >> 5;
    const int wm = wid >> 1, wn = wid & 1;
    const int g0 = lane >> 2, q = lane & 3;
    const int nitems = g_tileoff[NEXP] * 16;
    const int nchunk = HDIM / KC;           // 8

    const int ri    = lane & 7;
    const int miA   = lane >> 3;            // 0..3
    const int rowoA = (miA & 1) * 8;
    const int khA   = miA >> 1;
    const int mi2   = (lane >> 3) & 1;
    uint32_t aRow[2], bRow[4], axk[4], bxk[4];
#pragma unroll
    for (int m = 0; m < 2; m++) aRow[m] = (uint32_t)((wm*32 + m*16 + rowoA + ri) * 128);
#pragma unroll
    for (int n = 0; n < 4; n++) bRow[n] = (uint32_t)((wn*32 + n*8 + ri) * 128);
#pragma unroll
    for (int kt = 0; kt < 4; kt++) {
        axk[kt] = (uint32_t)((((kt<<1) | khA) ^ ri) << 4);
        bxk[kt] = (uint32_t)((((kt<<1) | mi2) ^ ri) << 4);
    }

    const int ar = tid >> 1;                 // A row 0..127
    const int ab = (tid & 1) * 4;
    const int wr_ = tid >> 2;                // G/U row 0..63
    const int wb = (tid & 3) * 2;

    for (int item = blockIdx.x; item < nitems; item += gridDim.x) {
        const int tIdx = item >> 4;
        const int ht   = item & 15;
        int e = 0;
        while (g_tileoff[e+1] <= tIdx) e++;
        const int base  = g_off[e] + (tIdx - g_tileoff[e]) * 128;
        const int nrows = min(128, g_off[e+1] - base);

        __syncthreads();                      // protect rtok + stage buffers
        if (tid < 128) rtok[tid] = g_tok[base + min(tid, nrows-1)];
        __syncthreads();

        const __half* xr  = g_xh + (size_t)rtok[ar]*HDIM;
        const __half* wgB = g_wgh + ((size_t)e*H2DIM + (size_t)ht*64) * HDIM + (size_t)wr_*HDIM;
        const __half* wuB = g_wuh + ((size_t)e*H2DIM + (size_t)ht*64) * HDIM + (size_t)wr_*HDIM;

        auto stage = [&](int c) {
            const int s = c % NSTG;
            const int kb = c * KC;            // halves
            uint32_t da = sb + F1_A(s) + ar*128;
#pragma unroll
            for (int i = 0; i < 4; i++)
                cpa16(da + ((ab+i) ^ (ar&7))*16, xr + kb + (ab+i)*8);
            uint32_t dg = sb + F1_G(s) + wr_*128;
            uint32_t du = sb + F1_U(s) + wr_*128;
#pragma unroll
            for (int i = 0; i < 2; i++) {
                cpa16(dg + ((wb+i) ^ (wr_&7))*16, wgB + kb + (wb+i)*8);
                cpa16(du + ((wb+i) ^ (wr_&7))*16, wuB + kb + (wb+i)*8);
            }
        };

        float accG[2][4][4] = {}, accU[2][4][4] = {};

        stage(0); CP_COMMIT();
        stage(1); CP_COMMIT();

        for (int c = 0; c < nchunk; c++) {
            CP_WAIT1();
            __syncthreads();
            if (c + 2 < nchunk) stage(c + 2);
            CP_COMMIT();

            const int s = c % NSTG;
            const uint32_t pA = sb + F1_A(s);
            const uint32_t pG = sb + F1_G(s);
            const uint32_t pU = sb + F1_U(s);
#pragma unroll
            for (int kt = 0; kt < 4; kt++) {   // 4 x k16 = 64 halves
                uint32_t a[2][4], bg[4][2], bu[4][2];
#pragma unroll
                for (int m = 0; m < 2; m++)
                    ldsm4(a[m], pA + aRow[m] + axk[kt]);
#pragma unroll
                for (int n = 0; n < 4; n++) {
                    ldsm2(bg[n], pG + bRow[n] + bxk[kt]);
                    ldsm2(bu[n], pU + bRow[n] + bxk[kt]);
                }
#pragma unroll
                for (int m = 0; m < 2; m++)
#pragma unroll
                    for (int n = 0; n < 4; n++) {
                        mma16(accG[m][n], a[m], bg[n]);
                        mma16(accU[m][n], a[m], bu[n]);
                    }
            }
        }
        // epilogue: silu(G)*U -> g_hidden fp16
        {
#pragma unroll
            for (int m = 0; m < 2; m++) {
#pragma unroll
                for (int half = 0; half < 2; half++) {
                    const int row = wm*32 + m*16 + g0 + half*8;
                    if (row < nrows) {
                        __half2* drow = (__half2*)(g_hidden + (size_t)(base+row)*H2DIM
                                                   + ht*64 + wn*32);
#pragma unroll
                        for (int n = 0; n < 4; n++) {
                            float gg0 = accG[m][n][half*2+0], gg1 = accG[m][n][half*2+1];
                            float uu0 = accU[m][n][half*2+0], uu1 = accU[m][n][half*2+1];
                            float h0 = uu0 * gg0 / (1.f + __expf(-gg0));
                            float h1 = uu1 * gg1 / (1.f + __expf(-gg1));
                            drow[n*4 + q] = __floats2half2_rn(h0, h1);
                        }
                    }
                }
            }
        }
    }
}

// ---------------- 4) FFN2: out[tok] += tw * (hidden Wd^T), fused combine ----
// tile 128 slots x 128 out. 8 warps 4m x 2n, warp tile 32x64. K=1024.
// B fragments via ldmatrix.x4 (2 n-tiles per instr). Epilogue: RED.F32 to out.
// smem: A @1024 (3x16KB); W @50176 (3x16KB). tot 99328.
#define F2_A(s)  (1024  + (s)*16384)
#define F2_W(s)  (50176 + (s)*16384)

__global__ __launch_bounds__(256)
void ffn2_mma(float* __restrict__ out) {
    char* sm = smem_dyn;
    const uint32_t sb = smem_u32(sm);
    const int tid = threadIdx.x, lane = tid & 31, wid = tid >> 5;
    const int wm = wid >> 1, wn = wid & 1;
    const int g0 = lane >> 2, q = lane & 3;
    const int nitems = g_tileoff[NEXP] * 4;
    const int nchunk = H2DIM / KC;            // 16

    const int ri  = lane & 7;
    const int miA = lane >> 3;
    const int kh  = (lane >> 3) & 1;
    const int ntx = lane >> 4;
    uint32_t aRow[2], bRowP[4], axk[4], bxk[4];
#pragma unroll
    for (int m = 0; m < 2; m++)
        aRow[m] = (uint32_t)((wm*32 + m*16 + (miA & 1)*8 + ri) * 128);
#pragma unroll
    for (int p = 0; p < 4; p++)
        bRowP[p] = (uint32_t)((wn*64 + (2*p + ntx)*8 + ri) * 128);
#pragma unroll
    for (int kt = 0; kt < 4; kt++) {
        axk[kt] = (uint32_t)((((kt<<1) | (miA>>1)) ^ ri) << 4);
        bxk[kt] = (uint32_t)((((kt<<1) | kh) ^ ri) << 4);
    }

    const int ar = tid >> 1;                 // row 0..127 (A and W same map)
    const int ab = (tid & 1) * 4;

    for (int item = blockIdx.x; item < nitems; item += gridDim.x) {
        const int tIdx = item >> 2;
        const int ht   = item & 3;
        int e = 0;
        while (g_tileoff[e+1] <= tIdx) e++;
        const int base  = g_off[e] + (tIdx - g_tileoff[e]) * 128;
        const int nrows = min(128, g_off[e+1] - base);

        const __half* hr  = g_hidden + (size_t)(base + min(ar, nrows-1))*H2DIM;
        const __half* wdB = g_wdh + ((size_t)e*HDIM + (size_t)ht*128) * H2DIM + (size_t)ar*H2DIM;

        __syncthreads();                      // stage-buffer reuse fence

        auto stage = [&](int c) {
            const int s = c % NSTG;
            const int kb = c * KC;            // halves
            uint32_t da = sb + F2_A(s) + ar*128;
            uint32_t dw = sb + F2_W(s) + ar*128;
#pragma unroll
            for (int i = 0; i < 4; i++) {
                cpa16(da + ((ab+i) ^ (ar&7))*16, hr  + kb + (ab+i)*8);
                cpa16(dw + ((ab+i) ^ (ar&7))*16, wdB + kb + (ab+i)*8);
            }
        };

        float acc[2][8][4] = {};

        stage(0); CP_COMMIT();
        stage(1); CP_COMMIT();

        for (int c = 0; c < nchunk; c++) {
            CP_WAIT1();
            __syncthreads();
            if (c + 2 < nchunk) stage(c + 2);
            CP_COMMIT();

            const int s = c % NSTG;
            const uint32_t pA = sb + F2_A(s);
            const uint32_t pW = sb + F2_W(s);
#pragma unroll
            for (int kt = 0; kt < 4; kt++) {
                uint32_t a[2][4], bw[4][4];
#pragma unroll
                for (int m = 0; m < 2; m++)
                    ldsm4(a[m], pA + aRow[m] + axk[kt]);
#pragma unroll
                for (int p = 0; p < 4; p++)
                    ldsm4(bw[p], pW + bRowP[p] + bxk[kt]);
#pragma unroll
                for (int m = 0; m < 2; m++)
#pragma unroll
                    for (int p = 0; p < 4; p++)
#pragma unroll
                        for (int h = 0; h < 2; h++)
                            mma16(acc[m][2*p+h], a[m], &bw[p][2*h]);
            }
        }
        // epilogue: out[tok] += acc * tw  (RED.F32; combine fused)
        {
            const int q2 = q * 2;
#pragma unroll
            for (int m = 0; m < 2; m++) {
#pragma unroll
                for (int half = 0; half < 2; half++) {
                    const int row = wm*32 + m*16 + g0 + half*8;
                    if (row < nrows) {
                        const float tw = g_tw[base + row];
                        const int tok = g_tok[base + row];
                        float* drow = out + (size_t)tok*HDIM + ht*128 + wn*64;
#pragma unroll
                        for (int n = 0; n < 8; n++) {
                            atomicAdd(drow + n*8 + q2,     acc[m][n][half*2+0] * tw);
                            atomicAdd(drow + n*8 + q2 + 1, acc[m][n][half*2+1] * tw);
                        }
                    }
                }
            }
        }
    }
}

// ---------------- launch ----------------------------------------------------
extern "C" void kernel_launch(void* const* d_in, const int* in_sizes, int n_in,
                              void* d_out, int out_size) {
    const float* x  = (const float*)d_in[0];   // [2,1024,512]
    const float* gw = (const float*)d_in[1];   // [32,512]
    const float* wg = (const float*)d_in[2];   // [32,1024,512]
    const float* wu = (const float*)d_in[3];   // [32,1024,512]
    const float* wd = (const float*)d_in[4];   // [32,512,1024]
    float* out = (float*)d_out;                // [2,1024,512] f32

    static void *p_wgh = nullptr, *p_wuh = nullptr, *p_wdh = nullptr;
    static cudaStream_t sA = nullptr, sB = nullptr, sC = nullptr;
    static cudaEvent_t evRoot = nullptr, evA = nullptr, evB = nullptr, evC = nullptr;
    if (!p_wgh) {
        cudaGetSymbolAddress(&p_wgh, g_wgh);
        cudaGetSymbolAddress(&p_wuh, g_wuh);
        cudaGetSymbolAddress(&p_wdh, g_wdh);
        cudaFuncSetAttribute(gate_kernel, cudaFuncAttributeMaxDynamicSharedMemorySize, 65536);
        cudaFuncSetAttribute(ffn1_mma,    cudaFuncAttributeMaxDynamicSharedMemorySize, 99328);
        cudaFuncSetAttribute(ffn2_mma,    cudaFuncAttributeMaxDynamicSharedMemorySize, 99328);
        cudaStreamCreateWithFlags(&sA, cudaStreamNonBlocking);
        cudaStreamCreateWithFlags(&sB, cudaStreamNonBlocking);
        cudaStreamCreateWithFlags(&sC, cudaStreamNonBlocking);
        cudaEventCreateWithFlags(&evRoot, cudaEventDisableTiming);
        cudaEventCreateWithFlags(&evA,    cudaEventDisableTiming);
        cudaEventCreateWithFlags(&evB,    cudaEventDisableTiming);
        cudaEventCreateWithFlags(&evC,    cudaEventDisableTiming);
    }

    const int NW8 = NEXP*H2DIM*HDIM/8;   // 2097152

    // zero the output (ffn2 accumulates into it atomically)
    cudaMemsetAsync(out, 0, (size_t)out_size * sizeof(float), 0);

    // fork: A = gate(+x-cvt)+route; B = wd cvt; C = wu cvt; main = wg cvt
    cudaEventRecord(evRoot, 0);
    cudaStreamWaitEvent(sA, evRoot, 0);
    cudaStreamWaitEvent(sB, evRoot, 0);
    cudaStreamWaitEvent(sC, evRoot, 0);

    gate_kernel <<<128, 256, 65536, sA>>>(x, gw);
    route_kernel<<<1, 256, 0, sA>>>();
    cudaEventRecord(evA, sA);

    cvt_kernel<<<NW8/256, 256, 0, sB>>>((const float4*)wd, (uint4*)p_wdh, NW8);
    cudaEventRecord(evB, sB);

    cvt_kernel<<<NW8/256, 256, 0, sC>>>((const float4*)wu, (uint4*)p_wuh, NW8);
    cudaEventRecord(evC, sC);

    cvt_kernel<<<NW8/256, 256>>>((const float4*)wg, (uint4*)p_wgh, NW8);

    cudaStreamWaitEvent(0, evA, 0);      // join gate/route (incl. fp16 x)
    cudaStreamWaitEvent(0, evC, 0);      // join wu convert
    ffn1_mma<<<296, 256, 99328>>>();     // wd convert (stream B) overlaps here
    cudaStreamWaitEvent(0, evB, 0);      // join wd convert
    ffn2_mma<<<296, 256, 99328>>>(out);  // fused combine via atomics
}

// round 15
// speedup vs baseline: 1.0752x; 1.0161x over previous
#include <cuda_runtime.h>
#include <cuda_fp16.h>
#include <cstdint>

// Problem constants (FractalMoE: E=32, H=512, TOPK=4, B=2, S=1024)
#define NTOK   2048
#define HDIM   512
#define H2DIM  1024
#define NEXP   32
#define TOPK   4
#define NSLOT  (NTOK*TOPK)   // 8192
#define KC     64            // K-chunk per stage (64 halves = 128B/row)
#define NSTG   3             // cp.async pipeline depth

// ---------------- scratch (device globals; no allocation allowed) ----------
__device__ int    g_sel[NSLOT];
__device__ float  g_wn[NSLOT];
__device__ int    g_off[NEXP+1];
__device__ int    g_tileoff[NEXP+1];
__device__ int    g_tok[NSLOT];
__device__ float  g_tw[NSLOT];
__device__ __half g_hidden [(size_t)NSLOT*H2DIM];      // 16 MiB fp16
__device__ __half g_xh [(size_t)NTOK*HDIM];            // 2 MiB fp16 x
__device__ __half g_wgh[(size_t)NEXP*H2DIM*HDIM];      // 32 MiB fp16 w_gate
__device__ __half g_wuh[(size_t)NEXP*H2DIM*HDIM];      // 32 MiB fp16 w_up
__device__ __half g_wdh[(size_t)NEXP*HDIM*H2DIM];      // 32 MiB fp16 w_down

// ---------------- helpers ----------------------------------------------------
__device__ __forceinline__ uint32_t smem_u32(const void* p) {
    uint32_t a;
    asm("{ .reg .u64 t; cvta.to.shared.u64 t, %1; cvt.u32.u64 %0, t; }"
        : "=r"(a) : "l"(p));
    return a;
}
__device__ __forceinline__ void cpa16(uint32_t dst, const void* src) {
    asm volatile("cp.async.cg.shared.global [%0], [%1], 16;" :: "r"(dst), "l"(src));
}
#define CP_COMMIT() asm volatile("cp.async.commit_group;" ::: "memory")
#define CP_WAIT1()  asm volatile("cp.async.wait_group 1;" ::: "memory")

__device__ __forceinline__ void ldsm4(uint32_t r[4], uint32_t addr) {
    asm volatile("ldmatrix.sync.aligned.m8n8.x4.shared.b16 {%0,%1,%2,%3}, [%4];"
        : "=r"(r[0]), "=r"(r[1]), "=r"(r[2]), "=r"(r[3]) : "r"(addr));
}

// m16n8k16 row.col f32.f16.f16.f32
__device__ __forceinline__ void mma16(float d[4], const uint32_t a[4], const uint32_t b[2]) {
    asm volatile(
        "mma.sync.aligned.m16n8k16.row.col.f32.f16.f16.f32 "
        "{%0,%1,%2,%3},{%4,%5,%6,%7},{%8,%9},{%0,%1,%2,%3};"
        : "+f"(d[0]), "+f"(d[1]), "+f"(d[2]), "+f"(d[3])
        : "r"(a[0]), "r"(a[1]), "r"(a[2]), "r"(a[3]), "r"(b[0]), "r"(b[1]));
}

// Panels: row-major, 64 halves (128B) per row. 16B block b of row r stored at
// block b ^ (r&7). Conflict-free for cp.async 16B writes and LDSM row reads.

extern __shared__ char smem_dyn[];

// ---------------- 0) fp32 -> fp16 (RN) convert ------------------------------
__global__ void cvt_kernel(const float4* __restrict__ src, uint4* __restrict__ dst, int n8) {
    int i = blockIdx.x*blockDim.x + threadIdx.x;
    if (i >= n8) return;
    float4 a = src[2*i], b = src[2*i+1];
    __half2 h0 = __floats2half2_rn(a.x, a.y);
    __half2 h1 = __floats2half2_rn(a.z, a.w);
    __half2 h2 = __floats2half2_rn(b.x, b.y);
    __half2 h3 = __floats2half2_rn(b.z, b.w);
    uint4 o;
    o.x = *(uint32_t*)&h0; o.y = *(uint32_t*)&h1;
    o.z = *(uint32_t*)&h2; o.w = *(uint32_t*)&h3;
    dst[i] = o;
}

// ---------------- 1) gating: softmax + top-4 + renormalize -----------------
__global__ void gate_kernel(const float* __restrict__ x, const float* __restrict__ gw) {
    float* sgw = (float*)smem_dyn;   // [32][512] = 64KB
    for (int i = threadIdx.x; i < NEXP*HDIM/4; i += blockDim.x)
        ((float4*)sgw)[i] = ((const float4*)gw)[i];
    __syncthreads();
    int warp = threadIdx.x >> 5, lane = threadIdx.x & 31;
    for (int tt = 0; tt < 2; tt++) {
        int t = blockIdx.x*16 + warp*2 + tt;
        const float4* xv = (const float4*)(x + (size_t)t * HDIM);
        const float4* gv = (const float4*)(sgw + lane * HDIM);
        float acc = 0.f;
#pragma unroll 4
        for (int k = 0; k < HDIM/4; k++) {
            float4 a = xv[k], b = gv[k];
            acc += a.x*b.x + a.y*b.y + a.z*b.z + a.w*b.w;
        }
        float m = acc;
        for (int o = 16; o; o >>= 1) m = fmaxf(m, __shfl_xor_sync(0xffffffffu, m, o));
        float p = __expf(acc - m);
        float s = p;
        for (int o = 16; o; o >>= 1) s += __shfl_xor_sync(0xffffffffu, s, o);
        float prob = p / s;

        float cur = prob, wsum = 0.f;
        float wv[TOPK]; int iv[TOPK];
#pragma unroll
        for (int it = 0; it < TOPK; it++) {
            float v = cur; int idx = lane;
            for (int o = 16; o; o >>= 1) {
                float v2 = __shfl_xor_sync(0xffffffffu, v, o);
                int   i2 = __shfl_xor_sync(0xffffffffu, idx, o);
                if (v2 > v || (v2 == v && i2 < idx)) { v = v2; idx = i2; }
            }
            wv[it] = v; iv[it] = idx; wsum += v;
            if (lane == idx) cur = -1.0f;
        }
        if (lane == 0) {
#pragma unroll
            for (int it = 0; it < TOPK; it++) {
                g_sel[t*TOPK + it] = iv[it];
                g_wn [t*TOPK + it] = wv[it] / wsum;
            }
        }
    }
}

// ---------------- 2) routing (tiles of 128 rows) ----------------------------
__global__ void route_kernel() {
    __shared__ int cnt[NEXP], run[NEXP], off_s[NEXP+1];
    int tid = threadIdx.x;
    if (tid < NEXP) { cnt[tid] = 0; run[tid] = 0; }
    __syncthreads();
    for (int i = tid; i < NSLOT; i += blockDim.x)
        atomicAdd(&cnt[g_sel[i]], 1);
    __syncthreads();
    if (tid == 0) {
        int o = 0, to = 0;
        for (int e = 0; e < NEXP; e++) {
            off_s[e] = o; g_off[e] = o; g_tileoff[e] = to;
            o  += cnt[e];
            to += (cnt[e] + 127) >> 7;
        }
        off_s[NEXP] = o; g_off[NEXP] = o; g_tileoff[NEXP] = to;
    }
    __syncthreads();
    for (int i = tid; i < NSLOT; i += blockDim.x) {
        int e = g_sel[i];
        int p = atomicAdd(&run[e], 1) + off_s[e];
        g_tok[p] = i >> 2;
        g_tw [p] = g_wn[i];
    }
}

// ---------------- 3) FFN1: hidden = silu(x Wg^T) * (x Wu^T) -----------------
// tile 128 tok x 64 hid (dual G/U). 8 warps 4m x 2n, warp tile 32x32/matrix.
// B fragments via ldmatrix.x4 (2 n-tiles per instr).
// smem: rtok@0; A @1024 (3x16KB); G @50176 (3x8KB); U @74752 (3x8KB). tot 99328.
#define F1_A(s)  (1024  + (s)*16384)
#define F1_G(s)  (50176 + (s)*8192)
#define F1_U(s)  (74752 + (s)*8192)

__global__ __launch_bounds__(256)
void ffn1_mma() {
    char* sm = smem_dyn;
    int* rtok = (int*)sm;
    const uint32_t sb = smem_u32(sm);
    const int tid = threadIdx.x, lane = tid & 31, wid = tid >> 5;
    const int wm = wid >> 1, wn = wid & 1;
    const int g0 = lane >> 2, q = lane & 3;
    const int nitems = g_tileoff[NEXP] * 16;
    const int nchunk = HDIM / KC;           // 8

    // LDSM per-lane constants
    const int ri  = lane & 7;
    const int miA = lane >> 3;              // 0..3 (A: 4 matrices)
    const int kh  = (lane >> 3) & 1;        // B x4: k-half select
    const int ntx = lane >> 4;              // B x4: second-tile select
    uint32_t aRow[2], bRowP[2], axk[4], bxk[4];
#pragma unroll
    for (int m = 0; m < 2; m++)
        aRow[m] = (uint32_t)((wm*32 + m*16 + (miA & 1)*8 + ri) * 128);
#pragma unroll
    for (int p = 0; p < 2; p++)
        bRowP[p] = (uint32_t)((wn*32 + (2*p + ntx)*8 + ri) * 128);
#pragma unroll
    for (int kt = 0; kt < 4; kt++) {
        axk[kt] = (uint32_t)((((kt<<1) | (miA>>1)) ^ ri) << 4);
        bxk[kt] = (uint32_t)((((kt<<1) | kh) ^ ri) << 4);
    }

    const int ar = tid >> 1;                 // A row 0..127
    const int ab = (tid & 1) * 4;
    const int wr_ = tid >> 2;                // G/U row 0..63
    const int wb = (tid & 3) * 2;

    for (int item = blockIdx.x; item < nitems; item += gridDim.x) {
        const int tIdx = item >> 4;
        const int ht   = item & 15;
        int e = 0;
        while (g_tileoff[e+1] <= tIdx) e++;
        const int base  = g_off[e] + (tIdx - g_tileoff[e]) * 128;
        const int nrows = min(128, g_off[e+1] - base);

        __syncthreads();                      // protect rtok + stage buffers
        if (tid < 128) rtok[tid] = g_tok[base + min(tid, nrows-1)];
        __syncthreads();

        const __half* xr  = g_xh + (size_t)rtok[ar]*HDIM;
        const __half* wgB = g_wgh + ((size_t)e*H2DIM + (size_t)ht*64) * HDIM + (size_t)wr_*HDIM;
        const __half* wuB = g_wuh + ((size_t)e*H2DIM + (size_t)ht*64) * HDIM + (size_t)wr_*HDIM;

        auto stage = [&](int c) {
            const int s = c % NSTG;
            const int kb = c * KC;            // halves
            uint32_t da = sb + F1_A(s) + ar*128;
#pragma unroll
            for (int i = 0; i < 4; i++)
                cpa16(da + ((ab+i) ^ (ar&7))*16, xr + kb + (ab+i)*8);
            uint32_t dg = sb + F1_G(s) + wr_*128;
            uint32_t du = sb + F1_U(s) + wr_*128;
#pragma unroll
            for (int i = 0; i < 2; i++) {
                cpa16(dg + ((wb+i) ^ (wr_&7))*16, wgB + kb + (wb+i)*8);
                cpa16(du + ((wb+i) ^ (wr_&7))*16, wuB + kb + (wb+i)*8);
            }
        };

        float accG[2][4][4] = {}, accU[2][4][4] = {};

        stage(0); CP_COMMIT();
        stage(1); CP_COMMIT();

        for (int c = 0; c < nchunk; c++) {
            CP_WAIT1();
            __syncthreads();
            if (c + 2 < nchunk) stage(c + 2);
            CP_COMMIT();

            const int s = c % NSTG;
            const uint32_t pA = sb + F1_A(s);
            const uint32_t pG = sb + F1_G(s);
            const uint32_t pU = sb + F1_U(s);
#pragma unroll
            for (int kt = 0; kt < 4; kt++) {   // 4 x k16 = 64 halves
                uint32_t a[2][4], bg[2][4], bu[2][4];
#pragma unroll
                for (int m = 0; m < 2; m++)
                    ldsm4(a[m], pA + aRow[m] + axk[kt]);
#pragma unroll
                for (int p = 0; p < 2; p++) {
                    ldsm4(bg[p], pG + bRowP[p] + bxk[kt]);
                    ldsm4(bu[p], pU + bRowP[p] + bxk[kt]);
                }
#pragma unroll
                for (int m = 0; m < 2; m++)
#pragma unroll
                    for (int p = 0; p < 2; p++)
#pragma unroll
                        for (int h = 0; h < 2; h++) {
                            mma16(accG[m][2*p+h], a[m], &bg[p][2*h]);
                            mma16(accU[m][2*p+h], a[m], &bu[p][2*h]);
                        }
            }
        }
        // epilogue: silu(G)*U -> g_hidden fp16
        {
#pragma unroll
            for (int m = 0; m < 2; m++) {
#pragma unroll
                for (int half = 0; half < 2; half++) {
                    const int row = wm*32 + m*16 + g0 + half*8;
                    if (row < nrows) {
                        __half2* drow = (__half2*)(g_hidden + (size_t)(base+row)*H2DIM
                                                   + ht*64 + wn*32);
#pragma unroll
                        for (int n = 0; n < 4; n++) {
                            float gg0 = accG[m][n][half*2+0], gg1 = accG[m][n][half*2+1];
                            float uu0 = accU[m][n][half*2+0], uu1 = accU[m][n][half*2+1];
                            float h0 = uu0 * gg0 / (1.f + __expf(-gg0));
                            float h1 = uu1 * gg1 / (1.f + __expf(-gg1));
                            drow[n*4 + q] = __floats2half2_rn(h0, h1);
                        }
                    }
                }
            }
        }
    }
}

// ---------------- 4) FFN2: out[tok] += tw * (hidden Wd^T), fused combine ----
// tile 128 slots x 128 out. 8 warps 4m x 2n, warp tile 32x64. K=1024.
// B fragments via ldmatrix.x4 (2 n-tiles per instr). Epilogue: RED.F32 to out.
// smem: A @1024 (3x16KB); W @50176 (3x16KB). tot 99328.
#define F2_A(s)  (1024  + (s)*16384)
#define F2_W(s)  (50176 + (s)*16384)

__global__ __launch_bounds__(256)
void ffn2_mma(float* __restrict__ out) {
    char* sm = smem_dyn;
    const uint32_t sb = smem_u32(sm);
    const int tid = threadIdx.x, lane = tid & 31, wid = tid >> 5;
    const int wm = wid >> 1, wn = wid & 1;
    const int g0 = lane >> 2, q = lane & 3;
    const int nitems = g_tileoff[NEXP] * 4;
    const int nchunk = H2DIM / KC;            // 16

    const int ri  = lane & 7;
    const int miA = lane >> 3;
    const int kh  = (lane >> 3) & 1;
    const int ntx = lane >> 4;
    uint32_t aRow[2], bRowP[4], axk[4], bxk[4];
#pragma unroll
    for (int m = 0; m < 2; m++)
        aRow[m] = (uint32_t)((wm*32 + m*16 + (miA & 1)*8 + ri) * 128);
#pragma unroll
    for (int p = 0; p < 4; p++)
        bRowP[p] = (uint32_t)((wn*64 + (2*p + ntx)*8 + ri) * 128);
#pragma unroll
    for (int kt = 0; kt < 4; kt++) {
        axk[kt] = (uint32_t)((((kt<<1) | (miA>>1)) ^ ri) << 4);
        bxk[kt] = (uint32_t)((((kt<<1) | kh) ^ ri) << 4);
    }

    const int ar = tid >> 1;                 // row 0..127 (A and W same map)
    const int ab = (tid & 1) * 4;

    for (int item = blockIdx.x; item < nitems; item += gridDim.x) {
        const int tIdx = item >> 2;
        const int ht   = item & 3;
        int e = 0;
        while (g_tileoff[e+1] <= tIdx) e++;
        const int base  = g_off[e] + (tIdx - g_tileoff[e]) * 128;
        const int nrows = min(128, g_off[e+1] - base);

        const __half* hr  = g_hidden + (size_t)(base + min(ar, nrows-1))*H2DIM;
        const __half* wdB = g_wdh + ((size_t)e*HDIM + (size_t)ht*128) * H2DIM + (size_t)ar*H2DIM;

        __syncthreads();                      // stage-buffer reuse fence

        auto stage = [&](int c) {
            const int s = c % NSTG;
            const int kb = c * KC;            // halves
            uint32_t da = sb + F2_A(s) + ar*128;
            uint32_t dw = sb + F2_W(s) + ar*128;
#pragma unroll
            for (int i = 0; i < 4; i++) {
                cpa16(da + ((ab+i) ^ (ar&7))*16, hr  + kb + (ab+i)*8);
                cpa16(dw + ((ab+i) ^ (ar&7))*16, wdB + kb + (ab+i)*8);
            }
        };

        float acc[2][8][4] = {};

        stage(0); CP_COMMIT();
        stage(1); CP_COMMIT();

        for (int c = 0; c < nchunk; c++) {
            CP_WAIT1();
            __syncthreads();
            if (c + 2 < nchunk) stage(c + 2);
            CP_COMMIT();

            const int s = c % NSTG;
            const uint32_t pA = sb + F2_A(s);
            const uint32_t pW = sb + F2_W(s);
#pragma unroll
            for (int kt = 0; kt < 4; kt++) {
                uint32_t a[2][4], bw[4][4];
#pragma unroll
                for (int m = 0; m < 2; m++)
                    ldsm4(a[m], pA + aRow[m] + axk[kt]);
#pragma unroll
                for (int p = 0; p < 4; p++)
                    ldsm4(bw[p], pW + bRowP[p] + bxk[kt]);
#pragma unroll
                for (int m = 0; m < 2; m++)
#pragma unroll
                    for (int p = 0; p < 4; p++)
#pragma unroll
                        for (int h = 0; h < 2; h++)
                            mma16(acc[m][2*p+h], a[m], &bw[p][2*h]);
            }
        }
        // epilogue: out[tok] += acc * tw  (RED.F32; combine fused)
        {
            const int q2 = q * 2;
#pragma unroll
            for (int m = 0; m < 2; m++) {
#pragma unroll
                for (int half = 0; half < 2; half++) {
                    const int row = wm*32 + m*16 + g0 + half*8;
                    if (row < nrows) {
                        const float tw = g_tw[base + row];
                        const int tok = g_tok[base + row];
                        float* drow = out + (size_t)tok*HDIM + ht*128 + wn*64;
#pragma unroll
                        for (int n = 0; n < 8; n++) {
                            atomicAdd(drow + n*8 + q2,     acc[m][n][half*2+0] * tw);
                            atomicAdd(drow + n*8 + q2 + 1, acc[m][n][half*2+1] * tw);
                        }
                    }
                }
            }
        }
    }
}

// ---------------- launch ----------------------------------------------------
extern "C" void kernel_launch(void* const* d_in, const int* in_sizes, int n_in,
                              void* d_out, int out_size) {
    const float* x  = (const float*)d_in[0];   // [2,1024,512]
    const float* gw = (const float*)d_in[1];   // [32,512]
    const float* wg = (const float*)d_in[2];   // [32,1024,512]
    const float* wu = (const float*)d_in[3];   // [32,1024,512]
    const float* wd = (const float*)d_in[4];   // [32,512,1024]
    float* out = (float*)d_out;                // [2,1024,512] f32

    static void *p_xh = nullptr, *p_wgh = nullptr, *p_wuh = nullptr, *p_wdh = nullptr;
    static cudaStream_t sA = nullptr, sB = nullptr;
    static cudaEvent_t evRoot = nullptr, evA = nullptr, evB = nullptr;
    if (!p_xh) {
        cudaGetSymbolAddress(&p_xh,  g_xh);
        cudaGetSymbolAddress(&p_wgh, g_wgh);
        cudaGetSymbolAddress(&p_wuh, g_wuh);
        cudaGetSymbolAddress(&p_wdh, g_wdh);
        cudaFuncSetAttribute(gate_kernel, cudaFuncAttributeMaxDynamicSharedMemorySize, 65536);
        cudaFuncSetAttribute(ffn1_mma,    cudaFuncAttributeMaxDynamicSharedMemorySize, 99328);
        cudaFuncSetAttribute(ffn2_mma,    cudaFuncAttributeMaxDynamicSharedMemorySize, 99328);
        cudaStreamCreateWithFlags(&sA, cudaStreamNonBlocking);
        cudaStreamCreateWithFlags(&sB, cudaStreamNonBlocking);
        cudaEventCreateWithFlags(&evRoot, cudaEventDisableTiming);
        cudaEventCreateWithFlags(&evA,    cudaEventDisableTiming);
        cudaEventCreateWithFlags(&evB,    cudaEventDisableTiming);
    }

    const int NW8 = NEXP*H2DIM*HDIM/8;   // 2097152
    const int NX8 = NTOK*HDIM/8;         // 131072

    // zero the output (ffn2 accumulates into it atomically)
    cudaMemsetAsync(out, 0, (size_t)out_size * sizeof(float), 0);

    // fork: branch A = gate+route (fp32 inputs only); branch B = wd convert
    cudaEventRecord(evRoot, 0);
    cudaStreamWaitEvent(sA, evRoot, 0);
    cudaStreamWaitEvent(sB, evRoot, 0);

    gate_kernel <<<128, 256, 65536, sA>>>(x, gw);
    route_kernel<<<1, 256, 0, sA>>>();
    cudaEventRecord(evA, sA);

    cvt_kernel<<<NW8/256, 256, 0, sB>>>((const float4*)wd, (uint4*)p_wdh, NW8);
    cudaEventRecord(evB, sB);

    // main: conversions needed by ffn1
    cvt_kernel<<<NX8/256, 256>>>((const float4*)x,  (uint4*)p_xh,  NX8);
    cvt_kernel<<<NW8/256, 256>>>((const float4*)wg, (uint4*)p_wgh, NW8);
    cvt_kernel<<<NW8/256, 256>>>((const float4*)wu, (uint4*)p_wuh, NW8);

    cudaStreamWaitEvent(0, evA, 0);      // join gate/route
    ffn1_mma<<<296, 256, 99328>>>();     // wd convert (branch B) overlaps here
    cudaStreamWaitEvent(0, evB, 0);      // join wd convert
    ffn2_mma<<<296, 256, 99328>>>(out);  // fused combine via atomics
}

// round 16
// speedup vs baseline: 1.1700x; 1.0882x over previous
#include <cuda_runtime.h>
#include <cuda_fp16.h>
#include <cstdint>

// Problem constants (FractalMoE: E=32, H=512, TOPK=4, B=2, S=1024)
#define NTOK   2048
#define HDIM   512
#define H2DIM  1024
#define NEXP   32
#define TOPK   4
#define NSLOT  (NTOK*TOPK)   // 8192
#define KC     64            // K-chunk per stage (64 halves = 128B/row)
#define NSTG   3             // cp.async pipeline depth

// ---------------- scratch (device globals; no allocation allowed) ----------
__device__ int    g_sel[NSLOT];
__device__ float  g_wn[NSLOT];
__device__ int    g_off[NEXP+1];
__device__ int    g_tileoff[NEXP+1];
__device__ int    g_tok[NSLOT];
__device__ float  g_tw[NSLOT];
__device__ __half g_hidden [(size_t)NSLOT*H2DIM];      // 16 MiB fp16
__device__ __half g_xh [(size_t)NTOK*HDIM];            // 2 MiB fp16 x
__device__ __half g_wgh[(size_t)NEXP*H2DIM*HDIM];      // 32 MiB fp16 w_gate
__device__ __half g_wuh[(size_t)NEXP*H2DIM*HDIM];      // 32 MiB fp16 w_up
__device__ __half g_wdh[(size_t)NEXP*HDIM*H2DIM];      // 32 MiB fp16 w_down

// ---------------- helpers ----------------------------------------------------
__device__ __forceinline__ uint32_t smem_u32(const void* p) {
    uint32_t a;
    asm("{ .reg .u64 t; cvta.to.shared.u64 t, %1; cvt.u32.u64 %0, t; }"
        : "=r"(a) : "l"(p));
    return a;
}
__device__ __forceinline__ void cpa16(uint32_t dst, const void* src) {
    asm volatile("cp.async.cg.shared.global [%0], [%1], 16;" :: "r"(dst), "l"(src));
}
#define CP_COMMIT() asm volatile("cp.async.commit_group;" ::: "memory")
#define CP_WAIT1()  asm volatile("cp.async.wait_group 1;" ::: "memory")

__device__ __forceinline__ void ldsm4(uint32_t r[4], uint32_t addr) {
    asm volatile("ldmatrix.sync.aligned.m8n8.x4.shared.b16 {%0,%1,%2,%3}, [%4];"
        : "=r"(r[0]), "=r"(r[1]), "=r"(r[2]), "=r"(r[3]) : "r"(addr));
}
__device__ __forceinline__ void ldsm2(uint32_t r[2], uint32_t addr) {
    asm volatile("ldmatrix.sync.aligned.m8n8.x2.shared.b16 {%0,%1}, [%2];"
        : "=r"(r[0]), "=r"(r[1]) : "r"(addr));
}

// m16n8k16 row.col f32.f16.f16.f32
__device__ __forceinline__ void mma16(float d[4], const uint32_t a[4], const uint32_t b[2]) {
    asm volatile(
        "mma.sync.aligned.m16n8k16.row.col.f32.f16.f16.f32 "
        "{%0,%1,%2,%3},{%4,%5,%6,%7},{%8,%9},{%0,%1,%2,%3};"
        : "+f"(d[0]), "+f"(d[1]), "+f"(d[2]), "+f"(d[3])
        : "r"(a[0]), "r"(a[1]), "r"(a[2]), "r"(a[3]), "r"(b[0]), "r"(b[1]));
}

// Panels: row-major, 64 halves (128B) per row. 16B block b of row r stored at
// block b ^ (r&7). Conflict-free for cp.async 16B writes and LDSM row reads.

extern __shared__ char smem_dyn[];

// ---------------- 0) fp32 -> fp16 (RN) convert ------------------------------
__global__ void cvt_kernel(const float4* __restrict__ src, uint4* __restrict__ dst, int n8) {
    int i = blockIdx.x*blockDim.x + threadIdx.x;
    if (i >= n8) return;
    float4 a = src[2*i], b = src[2*i+1];
    __half2 h0 = __floats2half2_rn(a.x, a.y);
    __half2 h1 = __floats2half2_rn(a.z, a.w);
    __half2 h2 = __floats2half2_rn(b.x, b.y);
    __half2 h3 = __floats2half2_rn(b.z, b.w);
    uint4 o;
    o.x = *(uint32_t*)&h0; o.y = *(uint32_t*)&h1;
    o.z = *(uint32_t*)&h2; o.w = *(uint32_t*)&h3;
    dst[i] = o;
}

// ---------------- 1) gating: softmax + top-4 + renorm; also emits fp16 x ----
__global__ void gate_kernel(const float* __restrict__ x, const float* __restrict__ gw) {
    float* sgw = (float*)smem_dyn;   // [32][512] = 64KB
    for (int i = threadIdx.x; i < NEXP*HDIM/4; i += blockDim.x)
        ((float4*)sgw)[i] = ((const float4*)gw)[i];

    // by-product: convert this block's 16 tokens to fp16 (x -> g_xh)
    {
        const float2* xblk = (const float2*)(x + (size_t)blockIdx.x*16*HDIM);
        __half2* dst = (__half2*)(g_xh + (size_t)blockIdx.x*16*HDIM);
        for (int i = threadIdx.x; i < 16*HDIM/2; i += blockDim.x) {
            float2 v = xblk[i];
            dst[i] = __floats2half2_rn(v.x, v.y);
        }
    }
    __syncthreads();
    int warp = threadIdx.x >> 5, lane = threadIdx.x & 31;
    for (int tt = 0; tt < 2; tt++) {
        int t = blockIdx.x*16 + warp*2 + tt;
        const float4* xv = (const float4*)(x + (size_t)t * HDIM);
        const float4* gv = (const float4*)(sgw + lane * HDIM);
        float acc = 0.f;
#pragma unroll 4
        for (int k = 0; k < HDIM/4; k++) {
            float4 a = xv[k], b = gv[k];
            acc += a.x*b.x + a.y*b.y + a.z*b.z + a.w*b.w;
        }
        float m = acc;
        for (int o = 16; o; o >>= 1) m = fmaxf(m, __shfl_xor_sync(0xffffffffu, m, o));
        float p = __expf(acc - m);
        float s = p;
        for (int o = 16; o; o >>= 1) s += __shfl_xor_sync(0xffffffffu, s, o);
        float prob = p / s;

        float cur = prob, wsum = 0.f;
        float wv[TOPK]; int iv[TOPK];
#pragma unroll
        for (int it = 0; it < TOPK; it++) {
            float v = cur; int idx = lane;
            for (int o = 16; o; o >>= 1) {
                float v2 = __shfl_xor_sync(0xffffffffu, v, o);
                int   i2 = __shfl_xor_sync(0xffffffffu, idx, o);
                if (v2 > v || (v2 == v && i2 < idx)) { v = v2; idx = i2; }
            }
            wv[it] = v; iv[it] = idx; wsum += v;
            if (lane == idx) cur = -1.0f;
        }
        if (lane == 0) {
#pragma unroll
            for (int it = 0; it < TOPK; it++) {
                g_sel[t*TOPK + it] = iv[it];
                g_wn [t*TOPK + it] = wv[it] / wsum;
            }
        }
    }
}

// ---------------- 2) routing (tiles of 128 rows) ----------------------------
__global__ void route_kernel() {
    __shared__ int cnt[NEXP], run[NEXP], off_s[NEXP+1];
    int tid = threadIdx.x;
    if (tid < NEXP) { cnt[tid] = 0; run[tid] = 0; }
    __syncthreads();
    for (int i = tid; i < NSLOT; i += blockDim.x)
        atomicAdd(&cnt[g_sel[i]], 1);
    __syncthreads();
    if (tid == 0) {
        int o = 0, to = 0;
        for (int e = 0; e < NEXP; e++) {
            off_s[e] = o; g_off[e] = o; g_tileoff[e] = to;
            o  += cnt[e];
            to += (cnt[e] + 127) >> 7;
        }
        off_s[NEXP] = o; g_off[NEXP] = o; g_tileoff[NEXP] = to;
    }
    __syncthreads();
    for (int i = tid; i < NSLOT; i += blockDim.x) {
        int e = g_sel[i];
        int p = atomicAdd(&run[e], 1) + off_s[e];
        g_tok[p] = i >> 2;
        g_tw [p] = g_wn[i];
    }
}

// ---------------- 3) FFN1: hidden = silu(x Wg^T) * (x Wu^T) -----------------
// tile 128 tok x 64 hid (dual G/U). 8 warps 4m x 2n, warp tile 32x32/matrix.
// Item order ht-major: all tiles sharing a weight slice run adjacently (L2 reuse).
// smem: rtok@0; A @1024 (3x16KB); G @50176 (3x8KB); U @74752 (3x8KB). tot 99328.
#define F1_A(s)  (1024  + (s)*16384)
#define F1_G(s)  (50176 + (s)*8192)
#define F1_U(s)  (74752 + (s)*8192)

__global__ __launch_bounds__(256)
void ffn1_mma() {
    char* sm = smem_dyn;
    int* rtok = (int*)sm;
    const uint32_t sb = smem_u32(sm);
    const int tid = threadIdx.x, lane = tid & 31, wid = tid >> 5;
    const int wm = wid >> 1, wn = wid & 1;
    const int g0 = lane >> 2, q = lane & 3;
    const int ntiles = g_tileoff[NEXP];
    const int nitems = ntiles * 16;
    const int nchunk = HDIM / KC;           // 8

    const int ri    = lane & 7;
    const int miA   = lane >> 3;            // 0..3
    const int rowoA = (miA & 1) * 8;
    const int khA   = miA >> 1;
    const int mi2   = (lane >> 3) & 1;
    uint32_t aRow[2], bRow[4], axk[4], bxk[4];
#pragma unroll
    for (int m = 0; m < 2; m++) aRow[m] = (uint32_t)((wm*32 + m*16 + rowoA + ri) * 128);
#pragma unroll
    for (int n = 0; n < 4; n++) bRow[n] = (uint32_t)((wn*32 + n*8 + ri) * 128);
#pragma unroll
    for (int kt = 0; kt < 4; kt++) {
        axk[kt] = (uint32_t)((((kt<<1) | khA) ^ ri) << 4);
        bxk[kt] = (uint32_t)((((kt<<1) | mi2) ^ ri) << 4);
    }

    const int ar = tid >> 1;                 // A row 0..127
    const int ab = (tid & 1) * 4;
    const int wr_ = tid >> 2;                // G/U row 0..63
    const int wb = (tid & 3) * 2;

    for (int item = blockIdx.x; item < nitems; item += gridDim.x) {
        const int ht   = item / ntiles;      // ht-major order for weight L2 reuse
        const int tIdx = item - ht * ntiles;
        int e = 0;
        while (g_tileoff[e+1] <= tIdx) e++;
        const int base  = g_off[e] + (tIdx - g_tileoff[e]) * 128;
        const int nrows = min(128, g_off[e+1] - base);

        __syncthreads();                      // protect rtok + stage buffers
        if (tid < 128) rtok[tid] = g_tok[base + min(tid, nrows-1)];
        __syncthreads();

        const __half* xr  = g_xh + (size_t)rtok[ar]*HDIM;
        const __half* wgB = g_wgh + ((size_t)e*H2DIM + (size_t)ht*64) * HDIM + (size_t)wr_*HDIM;
        const __half* wuB = g_wuh + ((size_t)e*H2DIM + (size_t)ht*64) * HDIM + (size_t)wr_*HDIM;

        auto stage = [&](int c) {
            const int s = c % NSTG;
            const int kb = c * KC;            // halves
            uint32_t da = sb + F1_A(s) + ar*128;
#pragma unroll
            for (int i = 0; i < 4; i++)
                cpa16(da + ((ab+i) ^ (ar&7))*16, xr + kb + (ab+i)*8);
            uint32_t dg = sb + F1_G(s) + wr_*128;
            uint32_t du = sb + F1_U(s) + wr_*128;
#pragma unroll
            for (int i = 0; i < 2; i++) {
                cpa16(dg + ((wb+i) ^ (wr_&7))*16, wgB + kb + (wb+i)*8);
                cpa16(du + ((wb+i) ^ (wr_&7))*16, wuB + kb + (wb+i)*8);
            }
        };

        float accG[2][4][4] = {}, accU[2][4][4] = {};

        stage(0); CP_COMMIT();
        stage(1); CP_COMMIT();

        for (int c = 0; c < nchunk; c++) {
            CP_WAIT1();
            __syncthreads();
            if (c + 2 < nchunk) stage(c + 2);
            CP_COMMIT();

            const int s = c % NSTG;
            const uint32_t pA = sb + F1_A(s);
            const uint32_t pG = sb + F1_G(s);
            const uint32_t pU = sb + F1_U(s);
#pragma unroll
            for (int kt = 0; kt < 4; kt++) {   // 4 x k16 = 64 halves
                uint32_t a[2][4], bg[4][2], bu[4][2];
#pragma unroll
                for (int m = 0; m < 2; m++)
                    ldsm4(a[m], pA + aRow[m] + axk[kt]);
#pragma unroll
                for (int n = 0; n < 4; n++) {
                    ldsm2(bg[n], pG + bRow[n] + bxk[kt]);
                    ldsm2(bu[n], pU + bRow[n] + bxk[kt]);
                }
#pragma unroll
                for (int m = 0; m < 2; m++)
#pragma unroll
                    for (int n = 0; n < 4; n++) {
                        mma16(accG[m][n], a[m], bg[n]);
                        mma16(accU[m][n], a[m], bu[n]);
                    }
            }
        }
        // epilogue: silu(G)*U -> g_hidden fp16
        {
#pragma unroll
            for (int m = 0; m < 2; m++) {
#pragma unroll
                for (int half = 0; half < 2; half++) {
                    const int row = wm*32 + m*16 + g0 + half*8;
                    if (row < nrows) {
                        __half2* drow = (__half2*)(g_hidden + (size_t)(base+row)*H2DIM
                                                   + ht*64 + wn*32);
#pragma unroll
                        for (int n = 0; n < 4; n++) {
                            float gg0 = accG[m][n][half*2+0], gg1 = accG[m][n][half*2+1];
                            float uu0 = accU[m][n][half*2+0], uu1 = accU[m][n][half*2+1];
                            float h0 = uu0 * gg0 / (1.f + __expf(-gg0));
                            float h1 = uu1 * gg1 / (1.f + __expf(-gg1));
                            drow[n*4 + q] = __floats2half2_rn(h0, h1);
                        }
                    }
                }
            }
        }
    }
}

// ---------------- 4) FFN2: out[tok] += tw * (hidden Wd^T), fused combine ----
// tile 128 slots x 128 out. 8 warps 4m x 2n, warp tile 32x64. K=1024.
// B fragments via ldmatrix.x4 (2 n-tiles per instr). Epilogue: RED.F32 to out.
// smem: A @1024 (3x16KB); W @50176 (3x16KB). tot 99328.
#define F2_A(s)  (1024  + (s)*16384)
#define F2_W(s)  (50176 + (s)*16384)

__global__ __launch_bounds__(256)
void ffn2_mma(float* __restrict__ out) {
    char* sm = smem_dyn;
    const uint32_t sb = smem_u32(sm);
    const int tid = threadIdx.x, lane = tid & 31, wid = tid >> 5;
    const int wm = wid >> 1, wn = wid & 1;
    const int g0 = lane >> 2, q = lane & 3;
    const int nitems = g_tileoff[NEXP] * 4;
    const int nchunk = H2DIM / KC;            // 16

    const int ri  = lane & 7;
    const int miA = lane >> 3;
    const int kh  = (lane >> 3) & 1;
    const int ntx = lane >> 4;
    uint32_t aRow[2], bRowP[4], axk[4], bxk[4];
#pragma unroll
    for (int m = 0; m < 2; m++)
        aRow[m] = (uint32_t)((wm*32 + m*16 + (miA & 1)*8 + ri) * 128);
#pragma unroll
    for (int p = 0; p < 4; p++)
        bRowP[p] = (uint32_t)((wn*64 + (2*p + ntx)*8 + ri) * 128);
#pragma unroll
    for (int kt = 0; kt < 4; kt++) {
        axk[kt] = (uint32_t)((((kt<<1) | (miA>>1)) ^ ri) << 4);
        bxk[kt] = (uint32_t)((((kt<<1) | kh) ^ ri) << 4);
    }

    const int ar = tid >> 1;                 // row 0..127 (A and W same map)
    const int ab = (tid & 1) * 4;

    for (int item = blockIdx.x; item < nitems; item += gridDim.x) {
        const int tIdx = item >> 2;
        const int ht   = item & 3;
        int e = 0;
        while (g_tileoff[e+1] <= tIdx) e++;
        const int base  = g_off[e] + (tIdx - g_tileoff[e]) * 128;
        const int nrows = min(128, g_off[e+1] - base);

        const __half* hr  = g_hidden + (size_t)(base + min(ar, nrows-1))*H2DIM;
        const __half* wdB = g_wdh + ((size_t)e*HDIM + (size_t)ht*128) * H2DIM + (size_t)ar*H2DIM;

        __syncthreads();                      // stage-buffer reuse fence

        auto stage = [&](int c) {
            const int s = c % NSTG;
            const int kb = c * KC;            // halves
            uint32_t da = sb + F2_A(s) + ar*128;
            uint32_t dw = sb + F2_W(s) + ar*128;
#pragma unroll
            for (int i = 0; i < 4; i++) {
                cpa16(da + ((ab+i) ^ (ar&7))*16, hr  + kb + (ab+i)*8);
                cpa16(dw + ((ab+i) ^ (ar&7))*16, wdB + kb + (ab+i)*8);
            }
        };

        float acc[2][8][4] = {};

        stage(0); CP_COMMIT();
        stage(1); CP_COMMIT();

        for (int c = 0; c < nchunk; c++) {
            CP_WAIT1();
            __syncthreads();
            if (c + 2 < nchunk) stage(c + 2);
            CP_COMMIT();

            const int s = c % NSTG;
            const uint32_t pA = sb + F2_A(s);
            const uint32_t pW = sb + F2_W(s);
#pragma unroll
            for (int kt = 0; kt < 4; kt++) {
                uint32_t a[2][4], bw[4][4];
#pragma unroll
                for (int m = 0; m < 2; m++)
                    ldsm4(a[m], pA + aRow[m] + axk[kt]);
#pragma unroll
                for (int p = 0; p < 4; p++)
                    ldsm4(bw[p], pW + bRowP[p] + bxk[kt]);
#pragma unroll
                for (int m = 0; m < 2; m++)
#pragma unroll
                    for (int p = 0; p < 4; p++)
#pragma unroll
                        for (int h = 0; h < 2; h++)
                            mma16(acc[m][2*p+h], a[m], &bw[p][2*h]);
            }
        }
        // epilogue: out[tok] += acc * tw  (RED.F32; combine fused)
        {
            const int q2 = q * 2;
#pragma unroll
            for (int m = 0; m < 2; m++) {
#pragma unroll
                for (int half = 0; half < 2; half++) {
                    const int row = wm*32 + m*16 + g0 + half*8;
                    if (row < nrows) {
                        const float tw = g_tw[base + row];
                        const int tok = g_tok[base + row];
                        float* drow = out + (size_t)tok*HDIM + ht*128 + wn*64;
#pragma unroll
                        for (int n = 0; n < 8; n++) {
                            atomicAdd(drow + n*8 + q2,     acc[m][n][half*2+0] * tw);
                            atomicAdd(drow + n*8 + q2 + 1, acc[m][n][half*2+1] * tw);
                        }
                    }
                }
            }
        }
    }
}

// ---------------- launch ----------------------------------------------------
extern "C" void kernel_launch(void* const* d_in, const int* in_sizes, int n_in,
                              void* d_out, int out_size) {
    const float* x  = (const float*)d_in[0];   // [2,1024,512]
    const float* gw = (const float*)d_in[1];   // [32,512]
    const float* wg = (const float*)d_in[2];   // [32,1024,512]
    const float* wu = (const float*)d_in[3];   // [32,1024,512]
    const float* wd = (const float*)d_in[4];   // [32,512,1024]
    float* out = (float*)d_out;                // [2,1024,512] f32

    static void *p_wgh = nullptr, *p_wuh = nullptr, *p_wdh = nullptr;
    static cudaStream_t sA = nullptr, sB = nullptr;
    static cudaEvent_t evRoot = nullptr, evA = nullptr, evB = nullptr;
    if (!p_wgh) {
        cudaGetSymbolAddress(&p_wgh, g_wgh);
        cudaGetSymbolAddress(&p_wuh, g_wuh);
        cudaGetSymbolAddress(&p_wdh, g_wdh);
        cudaFuncSetAttribute(gate_kernel, cudaFuncAttributeMaxDynamicSharedMemorySize, 65536);
        cudaFuncSetAttribute(ffn1_mma,    cudaFuncAttributeMaxDynamicSharedMemorySize, 99328);
        cudaFuncSetAttribute(ffn2_mma,    cudaFuncAttributeMaxDynamicSharedMemorySize, 99328);
        cudaStreamCreateWithFlags(&sA, cudaStreamNonBlocking);
        cudaStreamCreateWithFlags(&sB, cudaStreamNonBlocking);
        cudaEventCreateWithFlags(&evRoot, cudaEventDisableTiming);
        cudaEventCreateWithFlags(&evA,    cudaEventDisableTiming);
        cudaEventCreateWithFlags(&evB,    cudaEventDisableTiming);
    }

    const int NW8 = NEXP*H2DIM*HDIM/8;   // 2097152

    // zero the output (ffn2 accumulates into it atomically)
    cudaMemsetAsync(out, 0, (size_t)out_size * sizeof(float), 0);

    // fork: branch A = gate(+x fp16)+route; branch B = wd convert
    cudaEventRecord(evRoot, 0);
    cudaStreamWaitEvent(sA, evRoot, 0);
    cudaStreamWaitEvent(sB, evRoot, 0);

    gate_kernel <<<128, 256, 65536, sA>>>(x, gw);
    route_kernel<<<1, 256, 0, sA>>>();
    cudaEventRecord(evA, sA);

    cvt_kernel<<<NW8/256, 256, 0, sB>>>((const float4*)wd, (uint4*)p_wdh, NW8);
    cudaEventRecord(evB, sB);

    // main: conversions needed by ffn1
    cvt_kernel<<<NW8/256, 256>>>((const float4*)wg, (uint4*)p_wgh, NW8);
    cvt_kernel<<<NW8/256, 256>>>((const float4*)wu, (uint4*)p_wuh, NW8);

    cudaStreamWaitEvent(0, evA, 0);      // join gate/route (incl. fp16 x)
    ffn1_mma<<<296, 256, 99328>>>();     // wd convert (branch B) overlaps here
    cudaStreamWaitEvent(0, evB, 0);      // join wd convert
    ffn2_mma<<<296, 256, 99328>>>(out);  // fused combine via atomics
}